// round 1
// baseline (speedup 1.0000x reference)
#include <cuda_runtime.h>
#include <cstdint>

#define B 16
#define S 2048
#define D 64
#define TR 16
#define TC 128
#define PITCH 76   // floats per smem row (304B): conflict-free for stride-32-col access

// ---------- device scratch (no allocs allowed) ----------
__device__ unsigned char g_mask[B * S];
__device__ int g_cidx[B][S];
__device__ int g_ccnt[B];

// ---------- packed f32x2 helpers ----------
__device__ __forceinline__ void ffma2(unsigned long long& d, unsigned long long a,
                                      unsigned long long b) {
    asm("fma.rn.f32x2 %0, %1, %2, %0;" : "+l"(d) : "l"(a), "l"(b));
}
__device__ __forceinline__ float hsum2(unsigned long long a) {
    float lo = __int_as_float((int)(a & 0xffffffffull));
    float hi = __int_as_float((int)(a >> 32));
    return lo + hi;
}
__device__ __forceinline__ unsigned long long pack2(float p) {
    unsigned int u = __float_as_uint(p);
    return (unsigned long long)u | ((unsigned long long)u << 32);
}

// ---------- mask dtype detection + compact column lists ----------
__global__ void build_mask_kernel(const void* mptr) {
    __shared__ int mode_s;
    const unsigned char* pb = (const unsigned char*)mptr;
    if (threadIdx.x == 0) {
        int ok_int = 1, ok_flt = 1;
        for (int i = 0; i < 256; i++) {
            unsigned char b0 = pb[4 * i + 0], b1 = pb[4 * i + 1];
            unsigned char b2 = pb[4 * i + 2], b3 = pb[4 * i + 3];
            if (!(b0 <= 1 && b1 == 0 && b2 == 0 && b3 == 0)) ok_int = 0;
            bool zf = (b0 == 0 && b1 == 0 && b2 == 0 && b3 == 0);
            bool of = (b0 == 0 && b1 == 0 && b2 == 0x80 && b3 == 0x3f);
            if (!(zf || of)) ok_flt = 0;
        }
        mode_s = ok_int ? 1 : (ok_flt ? 2 : 0);
    }
    __syncthreads();
    int mode = mode_s;
    for (int i = threadIdx.x; i < B * S; i += blockDim.x) {
        unsigned char m;
        if (mode == 1)      m = (((const int*)mptr)[i] != 0);
        else if (mode == 2) m = (((const float*)mptr)[i] != 0.0f);
        else                m = (pb[i] != 0);
        g_mask[i] = m;
    }
    __syncthreads();
    if (threadIdx.x < B) {
        int b = threadIdx.x, cnt = 0;
        for (int t = 0; t < S; t++)
            if (!g_mask[b * S + t]) g_cidx[b][cnt++] = t;
        g_ccnt[b] = cnt;
    }
}

// ---------- main attention kernel ----------
// smem layout (floats):
//   sQ   [TR*PITCH]   @ 0       (1216)
//   sK   [TC*PITCH]   @ 1216    (9728)
//   sV   [TC*PITCH]   @ 10944   (9728)
//   sP   [TR*S]       @ 20672   (32768)  dense exp(score) row buffer
//   sCol [TC] (int)   @ 53440
//   sInv [TR]         @ 53568
//   sAct [TR] (int)   @ 53584
// total 53600 floats = 214,400 B
#define SMEM_FLOATS 53600

extern __shared__ float smem[];

__global__ __launch_bounds__(256, 1)
void attn_kernel(const float* __restrict__ Q, const float* __restrict__ K,
                 const float* __restrict__ V, float* __restrict__ out) {
    const int b   = blockIdx.y;
    const int rb  = blockIdx.x;
    const int tid = threadIdx.x;
    const int row0 = rb * TR;

    float* sQ = smem;
    float* sK = smem + 1216;
    float* sV = smem + 10944;
    float* sP = smem + 20672;
    int*   sCol = (int*)(smem + 53440);
    float* sInv = smem + 53568;
    int*   sAct = (int*)(smem + 53584);
    __shared__ int sAny;

    if (tid == 0) {
        int any = 0;
        for (int r = 0; r < TR; r++) {
            int a = (g_mask[b * S + row0 + r] == 0);
            sAct[r] = a;
            any |= a;
        }
        sAny = any;
    }

    // zero the dense exp buffer
    {
        float4 z = {0.f, 0.f, 0.f, 0.f};
        float4* p4 = (float4*)sP;
        for (int i = tid; i < TR * S / 4; i += 256) p4[i] = z;
    }
    // load Q rows, pre-scaled by 1/sqrt(D)
    {
        int r = tid >> 4, f = tid & 15;  // 256 threads cover 16 rows x 16 float4
        const float4* q4 = (const float4*)(Q + ((size_t)b * S + row0 + r) * D);
        float4 q = q4[f];
        q.x *= 0.125f; q.y *= 0.125f; q.z *= 0.125f; q.w *= 0.125f;
        *(float4*)&sQ[r * PITCH + f * 4] = q;
    }
    __syncthreads();

    const int anyActive = sAny;
    const int ncols = g_ccnt[b];

    // PV mapping: thread owns (row r_pv, 4 output dims at tg*4)
    const int r_pv = tid >> 4, tg = tid & 15;
    const int actPV = sAct[r_pv];
    // QK mapping: warp owns a row pair; thread owns cols {cq, cq+32, cq+64, cq+96}
    const int rp = tid >> 5, cq = tid & 31;
    const int act0 = sAct[rp * 2], act1 = sAct[rp * 2 + 1];

    unsigned long long cA = 0ull, cB = 0ull;  // packed context accumulators (d0,d1),(d2,d3)

    if (anyActive) {
        for (int ct = 0; ct < ncols; ct += TC) {
            const int n = min(TC, ncols - ct);
            // cooperative gather of K/V rows for this tile's compact columns
            for (int idx = tid; idx < TC * 16; idx += 256) {
                int j = idx >> 4, f = idx & 15;
                float4 kv = {0.f, 0.f, 0.f, 0.f}, vv = {0.f, 0.f, 0.f, 0.f};
                if (j < n) {
                    int col = g_cidx[b][ct + j];
                    if (f == 0) sCol[j] = col;
                    const float4* kp = (const float4*)(K + ((size_t)b * S + col) * D);
                    const float4* vp = (const float4*)(V + ((size_t)b * S + col) * D);
                    kv = kp[f];
                    vv = vp[f];
                } else if (f == 0) {
                    sCol[j] = 0;
                }
                *(float4*)&sK[j * PITCH + f * 4] = kv;
                *(float4*)&sV[j * PITCH + f * 4] = vv;
            }
            __syncthreads();

            // ---- QK phase: scores + exp into dense sP ----
            if (act0 | act1) {
                unsigned long long ax[2][4], ay[2][4];
                #pragma unroll
                for (int rr = 0; rr < 2; rr++)
                    #pragma unroll
                    for (int ii = 0; ii < 4; ii++) { ax[rr][ii] = 0ull; ay[rr][ii] = 0ull; }
                #pragma unroll
                for (int dd = 0; dd < 16; dd++) {
                    ulonglong2 q0 = *(const ulonglong2*)&sQ[(rp * 2 + 0) * PITCH + dd * 4];
                    ulonglong2 q1 = *(const ulonglong2*)&sQ[(rp * 2 + 1) * PITCH + dd * 4];
                    #pragma unroll
                    for (int ii = 0; ii < 4; ii++) {
                        ulonglong2 kk = *(const ulonglong2*)&sK[(cq + 32 * ii) * PITCH + dd * 4];
                        ffma2(ax[0][ii], q0.x, kk.x);
                        ffma2(ay[0][ii], q0.y, kk.y);
                        ffma2(ax[1][ii], q1.x, kk.x);
                        ffma2(ay[1][ii], q1.y, kk.y);
                    }
                }
                #pragma unroll
                for (int rr = 0; rr < 2; rr++) {
                    if (!sAct[rp * 2 + rr]) continue;
                    #pragma unroll
                    for (int ii = 0; ii < 4; ii++) {
                        int c = cq + 32 * ii;
                        if (c < n) {
                            float s = hsum2(ax[rr][ii]) + hsum2(ay[rr][ii]);
                            sP[(rp * 2 + rr) * S + sCol[c]] = __expf(s);
                        }
                    }
                }
            }
            __syncthreads();

            // ---- PV phase: context accumulation ----
            if (actPV) {
                int j = 0;
                for (; j + 4 <= n; j += 4) {
                    #pragma unroll
                    for (int u = 0; u < 4; u++) {
                        float p = sP[r_pv * S + sCol[j + u]];
                        ulonglong2 v = *(const ulonglong2*)&sV[(j + u) * PITCH + tg * 4];
                        unsigned long long pp = pack2(p);
                        ffma2(cA, pp, v.x);
                        ffma2(cB, pp, v.y);
                    }
                }
                for (; j < n; j++) {
                    float p = sP[r_pv * S + sCol[j]];
                    ulonglong2 v = *(const ulonglong2*)&sV[j * PITCH + tg * 4];
                    unsigned long long pp = pack2(p);
                    ffma2(cA, pp, v.x);
                    ffma2(cB, pp, v.y);
                }
            }
            __syncthreads();
        }
    }

    // ---- row sums -> inverse ----
    {
        float ssum = 0.f;
        const float4* prow = (const float4*)&sP[r_pv * S];
        #pragma unroll 8
        for (int kk = 0; kk < 32; kk++) {
            float4 p = prow[kk * 16 + tg];
            ssum += (p.x + p.y) + (p.z + p.w);
        }
        #pragma unroll
        for (int off = 8; off >= 1; off >>= 1)
            ssum += __shfl_xor_sync(0xffffffffu, ssum, off);
        if (tg == 0) sInv[r_pv] = (ssum > 0.f) ? (1.f / ssum) : 0.f;
    }
    __syncthreads();

    const float inv = sInv[r_pv];

    // ---- write attn row (dense, normalized; masked rows/cols are exact 0) ----
    {
        float4* arow = (float4*)(out + (size_t)B * S * D + ((size_t)b * S + row0 + r_pv) * S);
        const float4* prow = (const float4*)&sP[r_pv * S];
        #pragma unroll 8
        for (int kk = 0; kk < 32; kk++) {
            float4 p = prow[kk * 16 + tg];
            p.x *= inv; p.y *= inv; p.z *= inv; p.w *= inv;
            arow[kk * 16 + tg] = p;
        }
    }
    // ---- write context ----
    {
        float2 a = make_float2(__int_as_float((int)(cA & 0xffffffffull)),
                               __int_as_float((int)(cA >> 32)));
        float2 c = make_float2(__int_as_float((int)(cB & 0xffffffffull)),
                               __int_as_float((int)(cB >> 32)));
        float4 r = make_float4(a.x * inv, a.y * inv, c.x * inv, c.y * inv);
        *(float4*)(out + ((size_t)b * S + row0 + r_pv) * D + tg * 4) = r;
    }
}

extern "C" void kernel_launch(void* const* d_in, const int* in_sizes, int n_in,
                              void* d_out, int out_size) {
    const float* Q = (const float*)d_in[0];
    const float* K = (const float*)d_in[1];
    const float* V = (const float*)d_in[2];
    const void*  M = d_in[3];
    float* out = (float*)d_out;

    cudaFuncSetAttribute(attn_kernel, cudaFuncAttributeMaxDynamicSharedMemorySize,
                         SMEM_FLOATS * sizeof(float));

    build_mask_kernel<<<1, 256>>>(M);
    dim3 grid(S / TR, B);
    attn_kernel<<<grid, 256, SMEM_FLOATS * sizeof(float)>>>(Q, K, V, out);
}

// round 2
// speedup vs baseline: 3.0095x; 3.0095x over previous
#include <cuda_runtime.h>
#include <cuda_fp16.h>
#include <cstdint>

#define B 16
#define S 2048
#define D 64
#define TR 32
#define TC 128
#define PITCH 76     // floats per K/V/Q smem row (304B): conflict-free stride-32 col access
#define NTHREADS 512

// ---------- device scratch ----------
__device__ unsigned char g_mask[B * S];
__device__ int g_cidx[B][S];
__device__ int g_ccnt[B];

// ---------- packed f32x2 helpers ----------
__device__ __forceinline__ void ffma2(unsigned long long& d, unsigned long long a,
                                      unsigned long long b) {
    asm("fma.rn.f32x2 %0, %1, %2, %0;" : "+l"(d) : "l"(a), "l"(b));
}
__device__ __forceinline__ float lo2(unsigned long long a) {
    return __int_as_float((int)(a & 0xffffffffull));
}
__device__ __forceinline__ float hi2(unsigned long long a) {
    return __int_as_float((int)(a >> 32));
}
__device__ __forceinline__ float hsum2(unsigned long long a) { return lo2(a) + hi2(a); }
__device__ __forceinline__ unsigned long long pack2(float p) {
    unsigned int u = __float_as_uint(p);
    return (unsigned long long)u | ((unsigned long long)u << 32);
}

// ---------- mask build: one CTA per batch, block-scan compaction ----------
__global__ void build_mask_kernel(const void* mptr) {
    const int b = blockIdx.x;
    const int tid = threadIdx.x;
    __shared__ int warpTot[8];
    __shared__ int modeS;
    const unsigned char* pb = (const unsigned char*)mptr;
    if (tid == 0) {
        int ok_int = 1, ok_flt = 1;
        for (int i = 0; i < 256; i++) {
            unsigned char b0 = pb[4*i], b1 = pb[4*i+1], b2 = pb[4*i+2], b3 = pb[4*i+3];
            if (!(b0 <= 1 && b1 == 0 && b2 == 0 && b3 == 0)) ok_int = 0;
            bool zf = (b0 == 0 && b1 == 0 && b2 == 0 && b3 == 0);
            bool of = (b0 == 0 && b1 == 0 && b2 == 0x80 && b3 == 0x3f);
            if (!(zf || of)) ok_flt = 0;
        }
        modeS = ok_int ? 1 : (ok_flt ? 2 : 0);
    }
    __syncthreads();
    const int mode = modeS;
    unsigned char mloc[8];
    int cnt = 0;
    #pragma unroll
    for (int k = 0; k < 8; k++) {
        int i = b * S + tid * 8 + k;
        unsigned char m;
        if (mode == 1)      m = (((const int*)mptr)[i] != 0);
        else if (mode == 2) m = (((const float*)mptr)[i] != 0.0f);
        else                m = (pb[i] != 0);
        mloc[k] = m;
        g_mask[i] = m;
        cnt += (m == 0);
    }
    int lane = tid & 31, w = tid >> 5;
    int x = cnt;
    #pragma unroll
    for (int off = 1; off < 32; off <<= 1) {
        int y = __shfl_up_sync(0xffffffffu, x, off);
        if (lane >= off) x += y;
    }
    if (lane == 31) warpTot[w] = x;
    __syncthreads();
    int wOff = 0;
    for (int ww = 0; ww < w; ww++) wOff += warpTot[ww];
    int pos = wOff + x - cnt;  // exclusive prefix for this thread
    #pragma unroll
    for (int k = 0; k < 8; k++)
        if (!mloc[k]) g_cidx[b][pos++] = tid * 8 + k;
    if (tid == 255) g_ccnt[b] = wOff + x;
}

// ---------- zero-fill masked rows (attn row + context row) ----------
__global__ void zero_rows_kernel(float* __restrict__ out) {
    const int b = blockIdx.y;
    const int row = blockIdx.x * 16 + (threadIdx.x >> 4);
    const int tg = threadIdx.x & 15;
    if (!g_mask[b * S + row]) return;
    float4 z = {0.f, 0.f, 0.f, 0.f};
    float4* arow = (float4*)(out + (size_t)B * S * D + ((size_t)b * S + row) * S);
    #pragma unroll 8
    for (int it = 0; it < 32; it++) arow[it * 16 + tg] = z;
    *(float4*)(out + ((size_t)b * S + row) * D + tg * 4) = z;
}

// ---------- main attention kernel ----------
// smem (float offsets):
//   sQ    @0      2432   (32 x 76)
//   sK    @2432   9728   (128 x 76)   [aliased by sCtx in epilogue]
//   sV    @12160  9728   (128 x 76)
//   sPh   @21888  32768  (32 x 2048 half, dense exp rows)
//   sPc   @54656  2048   (32 x 128 half, compact exp tile)
//   sCol  @56704  128
//   sWsum @56832  64
//   sInv  @56896  32
//   sOrig @56928  32
// total 56960 floats = 227,840 B
#define SMEM_FLOATS 56960

extern __shared__ float smem[];

__global__ __launch_bounds__(NTHREADS, 1)
void attn_kernel(const float* __restrict__ Q, const float* __restrict__ K,
                 const float* __restrict__ V, float* __restrict__ out) {
    const int b = blockIdx.y;
    const int ncols = g_ccnt[b];
    const int row0c = blockIdx.x * TR;
    if (row0c >= ncols) return;
    const int nrows = min(TR, ncols - row0c);
    const int tid = threadIdx.x;

    float*  sQ   = smem;
    float*  sK   = smem + 2432;
    float*  sV   = smem + 12160;
    __half* sPh  = (__half*)(smem + 21888);
    __half* sPc  = (__half*)(smem + 54656);
    int*    sCol = (int*)(smem + 56704);
    float*  sWsum= smem + 56832;
    float*  sInv = smem + 56896;
    int*    sOrig= (int*)(smem + 56928);
    float4* sCtx = (float4*)sK;   // alias: used only after last tile

    // Q load (pre-scaled), record original row indices
    {
        int r = tid >> 4, f = tid & 15;
        float4 q = {0.f, 0.f, 0.f, 0.f};
        if (r < nrows) {
            int orig = g_cidx[b][row0c + r];
            if (f == 0) sOrig[r] = orig;
            q = ((const float4*)(Q + ((size_t)b * S + orig) * D))[f];
            q.x *= 0.125f; q.y *= 0.125f; q.z *= 0.125f; q.w *= 0.125f;
        }
        *(float4*)&sQ[r * PITCH + f * 4] = q;
    }
    // zero dense exp buffer (131072 B = 8192 float4)
    {
        float4 z = {0.f, 0.f, 0.f, 0.f};
        float4* p4 = (float4*)sPh;
        for (int i = tid; i < 8192; i += NTHREADS) p4[i] = z;
    }
    __syncthreads();

    const int w = tid >> 5, lane = tid & 31;
    const int rq = w & 7, ch = w >> 3;
    const int c0 = 64 * ch + lane;           // QK cols: c0, c0+32
    const int tg = lane & 15;
    const int pr0 = rq * 4 + (lane >> 4) * 2; // PV rows: pr0, pr0+1

    float sumAcc[4] = {0.f, 0.f, 0.f, 0.f};
    unsigned long long ctxA[2] = {0ull, 0ull}, ctxB[2] = {0ull, 0ull};

    for (int ct = 0; ct < ncols; ct += TC) {
        const int n = min(TC, ncols - ct);
        // gather K/V rows for compact columns
        for (int idx = tid; idx < TC * 16; idx += NTHREADS) {
            int j = idx >> 4, f = idx & 15;
            float4 kv = {0.f, 0.f, 0.f, 0.f}, vv = {0.f, 0.f, 0.f, 0.f};
            if (j < n) {
                int col = g_cidx[b][ct + j];
                if (f == 0) sCol[j] = col;
                kv = ((const float4*)(K + ((size_t)b * S + col) * D))[f];
                vv = ((const float4*)(V + ((size_t)b * S + col) * D))[f];
            }
            *(float4*)&sK[j * PITCH + f * 4] = kv;
            *(float4*)&sV[j * PITCH + f * 4] = vv;
        }
        // zero compact exp tile (8192 B = 1024 uint2)
        {
            uint2 z2 = make_uint2(0u, 0u);
            ((uint2*)sPc)[tid] = z2;
            ((uint2*)sPc)[tid + 512] = z2;
        }
        __syncthreads();

        // ---- QK: 4 rows x 2 cols per thread ----
        {
            unsigned long long ax[4][2], ay[4][2];
            #pragma unroll
            for (int r = 0; r < 4; r++) { ax[r][0]=ax[r][1]=ay[r][0]=ay[r][1]=0ull; }
            #pragma unroll
            for (int dd = 0; dd < 16; dd++) {
                ulonglong2 k0 = *(const ulonglong2*)&sK[c0 * PITCH + dd * 4];
                ulonglong2 k1 = *(const ulonglong2*)&sK[(c0 + 32) * PITCH + dd * 4];
                #pragma unroll
                for (int r = 0; r < 4; r++) {
                    ulonglong2 q = *(const ulonglong2*)&sQ[(rq * 4 + r) * PITCH + dd * 4];
                    ffma2(ax[r][0], q.x, k0.x);
                    ffma2(ay[r][0], q.y, k0.y);
                    ffma2(ax[r][1], q.x, k1.x);
                    ffma2(ay[r][1], q.y, k1.y);
                }
            }
            #pragma unroll
            for (int r = 0; r < 4; r++) {
                int row = rq * 4 + r;
                bool rok = (row < nrows);
                #pragma unroll
                for (int cc = 0; cc < 2; cc++) {
                    int c = c0 + 32 * cc;
                    if (rok && c < n) {
                        float s = hsum2(ax[r][cc]) + hsum2(ay[r][cc]);
                        float e = __expf(s);
                        sumAcc[r] += e;
                        __half eh = __float2half_rn(e);
                        sPh[row * S + sCol[c]] = eh;
                        sPc[row * TC + c] = eh;
                    }
                }
            }
        }
        __syncthreads();

        // ---- PV: 2 rows x (64-col half, 2 cols/iter) per thread ----
        {
            const int jend = min(n, 64 * ch + 64);
            for (int j = 64 * ch; j < jend; j += 2) {
                __half2 p0h = *(const __half2*)&sPc[pr0 * TC + j];
                __half2 p1h = *(const __half2*)&sPc[(pr0 + 1) * TC + j];
                float2 f0 = __half22float2(p0h);
                float2 f1 = __half22float2(p1h);
                ulonglong2 va = *(const ulonglong2*)&sV[j * PITCH + tg * 4];
                ulonglong2 vb = *(const ulonglong2*)&sV[(j + 1) * PITCH + tg * 4];
                unsigned long long pj;
                pj = pack2(f0.x); ffma2(ctxA[0], pj, va.x); ffma2(ctxB[0], pj, va.y);
                pj = pack2(f0.y); ffma2(ctxA[0], pj, vb.x); ffma2(ctxB[0], pj, vb.y);
                pj = pack2(f1.x); ffma2(ctxA[1], pj, va.x); ffma2(ctxB[1], pj, va.y);
                pj = pack2(f1.y); ffma2(ctxA[1], pj, vb.x); ffma2(ctxB[1], pj, vb.y);
            }
        }
        __syncthreads();
    }

    // ---- row sums -> inverse ----
    #pragma unroll
    for (int r = 0; r < 4; r++) {
        float v = sumAcc[r];
        #pragma unroll
        for (int off = 16; off >= 1; off >>= 1)
            v += __shfl_xor_sync(0xffffffffu, v, off);
        if (lane == 0) sWsum[w * 4 + r] = v;
    }
    __syncthreads();
    if (tid < TR) {
        int r = tid;
        float tot = sWsum[(r >> 2) * 4 + (r & 3)] + sWsum[((r >> 2) + 8) * 4 + (r & 3)];
        sInv[r] = (tot > 0.f) ? (1.f / tot) : 0.f;
    }
    __syncthreads();

    // ---- context: combine col-halves via smem (aliased over dead sK), write ----
    if (ch == 0) {
        sCtx[pr0 * 16 + tg] =
            make_float4(lo2(ctxA[0]), hi2(ctxA[0]), lo2(ctxB[0]), hi2(ctxB[0]));
        sCtx[(pr0 + 1) * 16 + tg] =
            make_float4(lo2(ctxA[1]), hi2(ctxA[1]), lo2(ctxB[1]), hi2(ctxB[1]));
    }
    __syncthreads();
    if (ch == 1) {
        #pragma unroll
        for (int rr = 0; rr < 2; rr++) {
            int row = pr0 + rr;
            if (row < nrows) {
                float4 o = sCtx[row * 16 + tg];
                o.x += lo2(ctxA[rr]); o.y += hi2(ctxA[rr]);
                o.z += lo2(ctxB[rr]); o.w += hi2(ctxB[rr]);
                float inv = sInv[row];
                o.x *= inv; o.y *= inv; o.z *= inv; o.w *= inv;
                *(float4*)(out + ((size_t)b * S + sOrig[row]) * D + tg * 4) = o;
            }
        }
    }

    // ---- attn rows: fp16 -> f32 * inv, coalesced dense write ----
    {
        int r = tid >> 4;
        if (r < nrows) {
            float inv = sInv[r];
            int orig = sOrig[r];
            float4* dst = (float4*)(out + (size_t)B * S * D + ((size_t)b * S + orig) * S);
            const __half2* src = (const __half2*)&sPh[r * S];
            #pragma unroll 4
            for (int it = 0; it < 16; it++) {
                int c8 = (it * 16 + tg) * 8;  // col index in halves, 8 per iter
                const __half2* sp = src + (c8 >> 1);
                float2 t0 = __half22float2(sp[0]);
                float2 t1 = __half22float2(sp[1]);
                float2 t2 = __half22float2(sp[2]);
                float2 t3 = __half22float2(sp[3]);
                float4 o0 = make_float4(t0.x * inv, t0.y * inv, t1.x * inv, t1.y * inv);
                float4 o1 = make_float4(t2.x * inv, t2.y * inv, t3.x * inv, t3.y * inv);
                dst[(c8 >> 2)] = o0;
                dst[(c8 >> 2) + 1] = o1;
            }
        }
    }
}

extern "C" void kernel_launch(void* const* d_in, const int* in_sizes, int n_in,
                              void* d_out, int out_size) {
    const float* Q = (const float*)d_in[0];
    const float* K = (const float*)d_in[1];
    const float* V = (const float*)d_in[2];
    const void*  M = d_in[3];
    float* out = (float*)d_out;

    cudaFuncSetAttribute(attn_kernel, cudaFuncAttributeMaxDynamicSharedMemorySize,
                         SMEM_FLOATS * sizeof(float));

    build_mask_kernel<<<B, 256>>>(M);
    zero_rows_kernel<<<dim3(S / 16, B), 256>>>(out);
    dim3 grid(S / TR, B);
    attn_kernel<<<grid, NTHREADS, SMEM_FLOATS * sizeof(float)>>>(Q, K, V, out);
}

// round 3
// speedup vs baseline: 4.5702x; 1.5186x over previous
#include <cuda_runtime.h>
#include <cuda_fp16.h>
#include <cstdint>

#define B 16
#define S 2048
#define D 64
#define TR 32
#define TC 128
#define NTH 512

#define KP 72     // halves pitch for Q/K/V smem rows (144 B)
#define PCP 136   // halves pitch for compact P tile (272 B)

// byte offsets into dynamic smem
#define OFF_QH   0
#define OFF_QL   4608
#define OFF_KH   9216
#define OFF_KL   27648
#define OFF_VH   46080
#define OFF_PC   64512
#define OFF_PH   73216
#define OFF_COL  204288
#define OFF_WSUM 204800
#define OFF_INV  204928
#define OFF_ORIG 205056
#define SMEM_BYTES 205184

// ---------- device scratch ----------
__device__ unsigned char g_mask[B * S];
__device__ int g_cidx[B][S];
__device__ int g_ccnt[B];

// ---------- mma / ldmatrix helpers ----------
__device__ __forceinline__ void ldsm4(uint32_t& r0, uint32_t& r1, uint32_t& r2,
                                      uint32_t& r3, uint32_t addr) {
    asm volatile("ldmatrix.sync.aligned.m8n8.x4.shared.b16 {%0,%1,%2,%3}, [%4];"
                 : "=r"(r0), "=r"(r1), "=r"(r2), "=r"(r3) : "r"(addr));
}
__device__ __forceinline__ void ldsm2t(uint32_t& r0, uint32_t& r1, uint32_t addr) {
    asm volatile("ldmatrix.sync.aligned.m8n8.x2.trans.shared.b16 {%0,%1}, [%2];"
                 : "=r"(r0), "=r"(r1) : "r"(addr));
}
__device__ __forceinline__ void mma16816(float* d, uint32_t a0, uint32_t a1,
                                         uint32_t a2, uint32_t a3,
                                         uint32_t b0, uint32_t b1) {
    asm volatile(
        "mma.sync.aligned.m16n8k16.row.col.f32.f16.f16.f32 "
        "{%0,%1,%2,%3},{%4,%5,%6,%7},{%8,%9},{%0,%1,%2,%3};"
        : "+f"(d[0]), "+f"(d[1]), "+f"(d[2]), "+f"(d[3])
        : "r"(a0), "r"(a1), "r"(a2), "r"(a3), "r"(b0), "r"(b1));
}

// ---------- mask build: one CTA per batch, parallel dtype detect + block scan ----------
__global__ void build_mask_kernel(const void* mptr) {
    const int b = blockIdx.x;
    const int tid = threadIdx.x;
    __shared__ int warpTot[8];
    __shared__ int okInt, okFlt;
    const unsigned char* pb = (const unsigned char*)mptr;
    if (tid == 0) { okInt = 1; okFlt = 1; }
    __syncthreads();
    {
        unsigned char b0 = pb[4*tid], b1 = pb[4*tid+1], b2 = pb[4*tid+2], b3 = pb[4*tid+3];
        bool gi = (b0 <= 1 && b1 == 0 && b2 == 0 && b3 == 0);
        bool zf = (b0 == 0 && b1 == 0 && b2 == 0 && b3 == 0);
        bool of = (b0 == 0 && b1 == 0 && b2 == 0x80 && b3 == 0x3f);
        if (!gi) atomicExch(&okInt, 0);
        if (!(zf || of)) atomicExch(&okFlt, 0);
    }
    __syncthreads();
    const int mode = okInt ? 1 : (okFlt ? 2 : 0);
    unsigned char mloc[8];
    int cnt = 0;
    #pragma unroll
    for (int k = 0; k < 8; k++) {
        int i = b * S + tid * 8 + k;
        unsigned char m;
        if (mode == 1)      m = (((const int*)mptr)[i] != 0);
        else if (mode == 2) m = (((const float*)mptr)[i] != 0.0f);
        else                m = (pb[i] != 0);
        mloc[k] = m;
        g_mask[i] = m;
        cnt += (m == 0);
    }
    int lane = tid & 31, w = tid >> 5;
    int x = cnt;
    #pragma unroll
    for (int off = 1; off < 32; off <<= 1) {
        int y = __shfl_up_sync(0xffffffffu, x, off);
        if (lane >= off) x += y;
    }
    if (lane == 31) warpTot[w] = x;
    __syncthreads();
    int wOff = 0;
    for (int ww = 0; ww < w; ww++) wOff += warpTot[ww];
    int pos = wOff + x - cnt;
    #pragma unroll
    for (int k = 0; k < 8; k++)
        if (!mloc[k]) g_cidx[b][pos++] = tid * 8 + k;
    if (tid == 255) g_ccnt[b] = wOff + x;
}

// ---------- zero-fill masked rows ----------
__global__ void zero_rows_kernel(float* __restrict__ out) {
    const int b = blockIdx.y;
    const int row = blockIdx.x * 16 + (threadIdx.x >> 4);
    const int tg = threadIdx.x & 15;
    if (!g_mask[b * S + row]) return;
    float4 z = {0.f, 0.f, 0.f, 0.f};
    float4* arow = (float4*)(out + (size_t)B * S * D + ((size_t)b * S + row) * S);
    #pragma unroll 8
    for (int it = 0; it < 32; it++) arow[it * 16 + tg] = z;
    *(float4*)(out + ((size_t)b * S + row) * D + tg * 4) = z;
}

// ---------- main attention kernel (HMMA tensor path) ----------
extern __shared__ char smem[];

__global__ __launch_bounds__(NTH, 1)
void attn_kernel(const float* __restrict__ Q, const float* __restrict__ K,
                 const float* __restrict__ V, float* __restrict__ out) {
    const int b = blockIdx.y;
    const int ncols = g_ccnt[b];
    const int row0c = blockIdx.x * TR;
    if (row0c >= ncols) return;
    const int nrows = min(TR, ncols - row0c);
    const int tid = threadIdx.x;
    const int lane = tid & 31, w = tid >> 5;
    const int rg = w >> 3, cg = w & 7;

    __half* sPh  = (__half*)(smem + OFF_PH);
    __half* sPc  = (__half*)(smem + OFF_PC);
    int*    sCol = (int*)(smem + OFF_COL);
    float*  sWsum= (float*)(smem + OFF_WSUM);
    float*  sInv = (float*)(smem + OFF_INV);
    int*    sOrig= (int*)(smem + OFF_ORIG);

    const uint32_t smemBase = (uint32_t)__cvta_generic_to_shared(smem);

    if (tid < 32) sWsum[tid] = 0.f;

    // ---- Q load + fp16 split (pre-scaled by 1/8) ----
    {
        int r = tid >> 4, f = tid & 15;
        float4 q = {0.f, 0.f, 0.f, 0.f};
        if (r < nrows) {
            int orig = g_cidx[b][row0c + r];
            if (f == 0) sOrig[r] = orig;
            q = ((const float4*)(Q + ((size_t)b * S + orig) * D))[f];
            q.x *= 0.125f; q.y *= 0.125f; q.z *= 0.125f; q.w *= 0.125f;
        }
        __half hx = __float2half_rn(q.x), hy = __float2half_rn(q.y);
        __half hz = __float2half_rn(q.z), hw = __float2half_rn(q.w);
        float lx = q.x - __half2float(hx), ly = q.y - __half2float(hy);
        float lz = q.z - __half2float(hz), lw = q.w - __half2float(hw);
        __half2* dh = (__half2*)(smem + OFF_QH + ((size_t)r * KP + f * 4) * 2);
        dh[0] = __halves2half2(hx, hy);
        dh[1] = __halves2half2(hz, hw);
        __half2* dl = (__half2*)(smem + OFF_QL + ((size_t)r * KP + f * 4) * 2);
        dl[0] = __floats2half2_rn(lx, ly);
        dl[1] = __floats2half2_rn(lz, lw);
    }
    // zero dense attn-exp buffer (131072 B)
    {
        uint4 z = {0u, 0u, 0u, 0u};
        uint4* p = (uint4*)(smem + OFF_PH);
        for (int i = tid; i < 8192; i += NTH) p[i] = z;
    }
    __syncthreads();

    // ---- precomputed ldmatrix addresses ----
    const uint32_t aQoff = (uint32_t)(((rg * 16 + (lane & 15)) * KP + ((lane >> 4) << 3)) * 2);
    const uint32_t aQh = smemBase + OFF_QH + aQoff;
    const uint32_t aQl = smemBase + OFF_QL + aQoff;
    const uint32_t bKoff = (uint32_t)(((cg * 16 + (lane & 7) + ((lane >> 4) << 3)) * KP
                                      + (((lane >> 3) & 1) << 3)) * 2);
    const uint32_t bKh = smemBase + OFF_KH + bKoff;
    const uint32_t bKl = smemBase + OFF_KL + bKoff;
    const uint32_t aPaddr = smemBase + OFF_PC
        + (uint32_t)(((rg * 16 + (lane & 15)) * PCP + ((lane >> 4) << 3)) * 2);
    const uint32_t bVaddr = smemBase + OFF_VH + (uint32_t)(((lane & 15) * KP + cg * 8) * 2);

    const int rowE = rg * 16 + (lane >> 2);   // epilogue row (lo); +8 for hi
    const int colE = cg * 16 + ((lane & 3) << 1);

    float ctx[4] = {0.f, 0.f, 0.f, 0.f};
    float sumLo = 0.f, sumHi = 0.f;

    for (int ct = 0; ct < ncols; ct += TC) {
        const int n = min(TC, ncols - ct);

        // ---- gather K/V compact rows, convert to fp16 (K split hi/lo) ----
        for (int idx = tid; idx < TC * 16; idx += NTH) {
            int j = idx >> 4, f = idx & 15;
            float4 kv = {0.f, 0.f, 0.f, 0.f}, vv = {0.f, 0.f, 0.f, 0.f};
            if (j < n) {
                int col = g_cidx[b][ct + j];
                if (f == 0) sCol[j] = col;
                kv = ((const float4*)(K + ((size_t)b * S + col) * D))[f];
                vv = ((const float4*)(V + ((size_t)b * S + col) * D))[f];
            }
            __half h0 = __float2half_rn(kv.x), h1 = __float2half_rn(kv.y);
            __half h2 = __float2half_rn(kv.z), h3 = __float2half_rn(kv.w);
            float l0 = kv.x - __half2float(h0), l1 = kv.y - __half2float(h1);
            float l2 = kv.z - __half2float(h2), l3 = kv.w - __half2float(h3);
            size_t off = ((size_t)j * KP + f * 4) * 2;
            __half2* dKh = (__half2*)(smem + OFF_KH + off);
            dKh[0] = __halves2half2(h0, h1);
            dKh[1] = __halves2half2(h2, h3);
            __half2* dKl = (__half2*)(smem + OFF_KL + off);
            dKl[0] = __floats2half2_rn(l0, l1);
            dKl[1] = __floats2half2_rn(l2, l3);
            __half2* dV = (__half2*)(smem + OFF_VH + off);
            dV[0] = __floats2half2_rn(vv.x, vv.y);
            dV[1] = __floats2half2_rn(vv.z, vv.w);
        }
        __syncthreads();

        // ---- QK^T via HMMA: 3-pass fp16 split, C = 16x16 per warp ----
        float c0[4] = {0.f, 0.f, 0.f, 0.f};
        float c1[4] = {0.f, 0.f, 0.f, 0.f};
        #pragma unroll
        for (int kk = 0; kk < 4; kk++) {
            uint32_t ah0, ah1, ah2, ah3, al0, al1, al2, al3;
            uint32_t bh0, bh1, bh2, bh3, bl0, bl1, bl2, bl3;
            ldsm4(ah0, ah1, ah2, ah3, aQh + kk * 32);
            ldsm4(al0, al1, al2, al3, aQl + kk * 32);
            ldsm4(bh0, bh1, bh2, bh3, bKh + kk * 32);
            ldsm4(bl0, bl1, bl2, bl3, bKl + kk * 32);
            mma16816(c0, ah0, ah1, ah2, ah3, bh0, bh1);
            mma16816(c1, ah0, ah1, ah2, ah3, bh2, bh3);
            mma16816(c0, ah0, ah1, ah2, ah3, bl0, bl1);
            mma16816(c1, ah0, ah1, ah2, ah3, bl2, bl3);
            mma16816(c0, al0, al1, al2, al3, bh0, bh1);
            mma16816(c1, al0, al1, al2, al3, bh2, bh3);
        }

        // ---- exp epilogue: write compact P tile + dense attn buffer, row sums ----
        {
            const bool r0ok = (rowE < nrows), r1ok = (rowE + 8 < nrows);
            #pragma unroll
            for (int t = 0; t < 2; t++) {
                const float* cc = t ? c1 : c0;
                #pragma unroll
                for (int i = 0; i < 4; i++) {
                    int col = colE + t * 8 + (i & 1);
                    int row = rowE + ((i >> 1) << 3);
                    bool rok = (i >> 1) ? r1ok : r0ok;
                    float e = 0.f;
                    if (rok && col < n) {
                        e = __expf(cc[i]);
                        if (i >> 1) sumHi += e; else sumLo += e;
                        sPh[row * S + sCol[col]] = __float2half_rn(e);
                    }
                    sPc[row * PCP + col] = __float2half_rn(e);
                }
            }
        }
        __syncthreads();

        // ---- PV via HMMA: ctx(16x8 per warp) += P(16x128) * V(128x8col) ----
        #pragma unroll
        for (int kk = 0; kk < 8; kk++) {
            uint32_t a0, a1, a2, a3, b0, b1;
            ldsm4(a0, a1, a2, a3, aPaddr + kk * 32);
            ldsm2t(b0, b1, bVaddr + kk * 16 * (KP * 2));
            mma16816(ctx, a0, a1, a2, a3, b0, b1);
        }
        __syncthreads();
    }

    // ---- row-sum reduction: quad shuffle + atomic into sWsum ----
    sumLo += __shfl_xor_sync(0xffffffffu, sumLo, 1);
    sumLo += __shfl_xor_sync(0xffffffffu, sumLo, 2);
    sumHi += __shfl_xor_sync(0xffffffffu, sumHi, 1);
    sumHi += __shfl_xor_sync(0xffffffffu, sumHi, 2);
    if ((lane & 3) == 0) {
        atomicAdd(&sWsum[rowE], sumLo);
        atomicAdd(&sWsum[rowE + 8], sumHi);
    }
    __syncthreads();
    if (tid < 32) {
        float t = sWsum[tid];
        sInv[tid] = (t > 0.f) ? (1.f / t) : 0.f;
    }
    __syncthreads();

    // ---- context write ----
    {
        int colBase = cg * 8 + ((lane & 3) << 1);
        if (rowE < nrows) {
            float inv = sInv[rowE];
            float2 o = make_float2(ctx[0] * inv, ctx[1] * inv);
            *(float2*)(out + ((size_t)b * S + sOrig[rowE]) * D + colBase) = o;
        }
        if (rowE + 8 < nrows) {
            float inv = sInv[rowE + 8];
            float2 o = make_float2(ctx[2] * inv, ctx[3] * inv);
            *(float2*)(out + ((size_t)b * S + sOrig[rowE + 8]) * D + colBase) = o;
        }
    }

    // ---- attn rows: fp16 -> f32 * inv, coalesced dense write ----
    {
        int r = tid >> 4, tg = tid & 15;
        if (r < nrows) {
            float inv = sInv[r];
            int orig = sOrig[r];
            float4* dst = (float4*)(out + (size_t)B * S * D + ((size_t)b * S + orig) * S);
            const __half2* src = (const __half2*)&sPh[r * S];
            #pragma unroll 4
            for (int it = 0; it < 16; it++) {
                int c8 = (it * 16 + tg) * 8;
                const __half2* sp = src + (c8 >> 1);
                float2 t0 = __half22float2(sp[0]);
                float2 t1 = __half22float2(sp[1]);
                float2 t2 = __half22float2(sp[2]);
                float2 t3 = __half22float2(sp[3]);
                float4 o0 = make_float4(t0.x * inv, t0.y * inv, t1.x * inv, t1.y * inv);
                float4 o1 = make_float4(t2.x * inv, t2.y * inv, t3.x * inv, t3.y * inv);
                dst[(c8 >> 2)] = o0;
                dst[(c8 >> 2) + 1] = o1;
            }
        }
    }
}

extern "C" void kernel_launch(void* const* d_in, const int* in_sizes, int n_in,
                              void* d_out, int out_size) {
    const float* Q = (const float*)d_in[0];
    const float* K = (const float*)d_in[1];
    const float* V = (const float*)d_in[2];
    const void*  M = d_in[3];
    float* out = (float*)d_out;

    cudaFuncSetAttribute(attn_kernel, cudaFuncAttributeMaxDynamicSharedMemorySize,
                         SMEM_BYTES);

    build_mask_kernel<<<B, 256>>>(M);
    zero_rows_kernel<<<dim3(S / 16, B), 256>>>(out);
    dim3 grid(S / TR, B);
    attn_kernel<<<grid, NTH, SMEM_BYTES>>>(Q, K, V, out);
}

// round 4
// speedup vs baseline: 7.9539x; 1.7404x over previous
#include <cuda_runtime.h>
#include <cuda_fp16.h>
#include <cstdint>

#define B 16
#define S 2048
#define D 64
#define TR 32
#define TC 64
#define NTH 512
#define KP 72          // halves pitch for K/V/Q smem rows (144 B, ldsm conflict-free)
#define PP 2056        // halves pitch for dense compact P rows (4112 B)

// ---- smem byte offsets ----
#define OFF_PH    0                      // 32 x 2056 half = 131584
#define OFF_STAGE 131584                 // 2 stages x 27648
#define STG_STRIDE 27648
#define STG_KH 0
#define STG_KL 9216
#define STG_VH 18432
#define OFF_QH    186880                 // 4608
#define OFF_QL    191488                 // 4608
#define OFF_PINV  196096                 // 8192
#define OFF_WSUM  204288                 // 128
#define OFF_INV   204416                 // 128
#define OFF_ORIG  204544                 // 128
#define SMEM_BYTES 204672

// ---------- device scratch ----------
__device__ int g_cidx[B][S];     // compact col -> orig
__device__ int g_midx[B][S];     // masked rank -> orig
__device__ int g_pinv[B][S];     // orig -> compact col, or -1
__device__ int g_ccnt[B];
__device__ __half g_kh[(size_t)B * S * D];
__device__ __half g_kl[(size_t)B * S * D];
__device__ __half g_vh[(size_t)B * S * D];

// ---------- asm helpers ----------
__device__ __forceinline__ void ldsm4(uint32_t& r0, uint32_t& r1, uint32_t& r2,
                                      uint32_t& r3, uint32_t a) {
    asm volatile("ldmatrix.sync.aligned.m8n8.x4.shared.b16 {%0,%1,%2,%3}, [%4];"
                 : "=r"(r0), "=r"(r1), "=r"(r2), "=r"(r3) : "r"(a));
}
__device__ __forceinline__ void ldsm2(uint32_t& r0, uint32_t& r1, uint32_t a) {
    asm volatile("ldmatrix.sync.aligned.m8n8.x2.shared.b16 {%0,%1}, [%2];"
                 : "=r"(r0), "=r"(r1) : "r"(a));
}
__device__ __forceinline__ void ldsm2t(uint32_t& r0, uint32_t& r1, uint32_t a) {
    asm volatile("ldmatrix.sync.aligned.m8n8.x2.trans.shared.b16 {%0,%1}, [%2];"
                 : "=r"(r0), "=r"(r1) : "r"(a));
}
__device__ __forceinline__ void mma16816(float* d, uint32_t a0, uint32_t a1,
                                         uint32_t a2, uint32_t a3,
                                         uint32_t b0, uint32_t b1) {
    asm volatile(
        "mma.sync.aligned.m16n8k16.row.col.f32.f16.f16.f32 "
        "{%0,%1,%2,%3},{%4,%5,%6,%7},{%8,%9},{%0,%1,%2,%3};"
        : "+f"(d[0]), "+f"(d[1]), "+f"(d[2]), "+f"(d[3])
        : "r"(a0), "r"(a1), "r"(a2), "r"(a3), "r"(b0), "r"(b1));
}
__device__ __forceinline__ void cpa16(uint32_t saddr, const void* g) {
    asm volatile("cp.async.cg.shared.global [%0], [%1], 16;" :: "r"(saddr), "l"(g)
                 : "memory");
}
__device__ __forceinline__ void cpcommit() {
    asm volatile("cp.async.commit_group;" ::: "memory");
}
__device__ __forceinline__ void cpwait1() {
    asm volatile("cp.async.wait_group 1;" ::: "memory");
}

// ---------- mask build ----------
__global__ void build_mask_kernel(const void* mptr) {
    const int b = blockIdx.x;
    const int tid = threadIdx.x;
    __shared__ int warpTot[8];
    __shared__ int okInt, okFlt;
    const unsigned char* pb = (const unsigned char*)mptr;
    if (tid == 0) { okInt = 1; okFlt = 1; }
    __syncthreads();
    {
        unsigned char b0 = pb[4*tid], b1 = pb[4*tid+1], b2 = pb[4*tid+2], b3 = pb[4*tid+3];
        bool gi = (b0 <= 1 && b1 == 0 && b2 == 0 && b3 == 0);
        bool zf = (b0 == 0 && b1 == 0 && b2 == 0 && b3 == 0);
        bool of = (b0 == 0 && b1 == 0 && b2 == 0x80 && b3 == 0x3f);
        if (!gi) atomicExch(&okInt, 0);
        if (!(zf || of)) atomicExch(&okFlt, 0);
    }
    __syncthreads();
    const int mode = okInt ? 1 : (okFlt ? 2 : 0);
    unsigned char mloc[8];
    int cnt = 0;
    #pragma unroll
    for (int k = 0; k < 8; k++) {
        int i = b * S + tid * 8 + k;
        unsigned char m;
        if (mode == 1)      m = (((const int*)mptr)[i] != 0);
        else if (mode == 2) m = (((const float*)mptr)[i] != 0.0f);
        else                m = (pb[i] != 0);
        mloc[k] = m;
        cnt += (m == 0);
    }
    int lane = tid & 31, w = tid >> 5;
    int x = cnt;
    #pragma unroll
    for (int off = 1; off < 32; off <<= 1) {
        int y = __shfl_up_sync(0xffffffffu, x, off);
        if (lane >= off) x += y;
    }
    if (lane == 31) warpTot[w] = x;
    __syncthreads();
    int wOff = 0;
    for (int ww = 0; ww < w; ww++) wOff += warpTot[ww];
    int pos = wOff + x - cnt;
    #pragma unroll
    for (int k = 0; k < 8; k++) {
        int idx = tid * 8 + k;
        if (!mloc[k]) {
            g_cidx[b][pos] = idx;
            g_pinv[b][idx] = pos;
            pos++;
        } else {
            g_midx[b][idx - pos] = idx;
            g_pinv[b][idx] = -1;
        }
    }
    if (tid == 255) g_ccnt[b] = pos;
}

// ---------- preprocess: K/V -> fp16 (K split hi/lo) in compact order ----------
__global__ void preprocess_kernel(const float* __restrict__ K,
                                  const float* __restrict__ V) {
    const int b = blockIdx.y;
    const int tid = threadIdx.x;
    const int cc = blockIdx.x * 64 + (tid >> 2);
    const int qd = (tid & 3) * 16;
    const int nc = g_ccnt[b];
    __half* kh = g_kh + ((size_t)b * S + cc) * D + qd;
    __half* kl = g_kl + ((size_t)b * S + cc) * D + qd;
    __half* vh = g_vh + ((size_t)b * S + cc) * D + qd;
    if (cc < nc) {
        int orig = g_cidx[b][cc];
        const float4* kp = (const float4*)(K + ((size_t)b * S + orig) * D + qd);
        const float4* vp = (const float4*)(V + ((size_t)b * S + orig) * D + qd);
        #pragma unroll
        for (int j = 0; j < 4; j++) {
            float4 kv = kp[j], vv = vp[j];
            __half h0 = __float2half_rn(kv.x), h1 = __float2half_rn(kv.y);
            __half h2 = __float2half_rn(kv.z), h3 = __float2half_rn(kv.w);
            ((__half2*)(kh + j * 4))[0] = __halves2half2(h0, h1);
            ((__half2*)(kh + j * 4))[1] = __halves2half2(h2, h3);
            ((__half2*)(kl + j * 4))[0] =
                __floats2half2_rn(kv.x - __half2float(h0), kv.y - __half2float(h1));
            ((__half2*)(kl + j * 4))[1] =
                __floats2half2_rn(kv.z - __half2float(h2), kv.w - __half2float(h3));
            ((__half2*)(vh + j * 4))[0] = __floats2half2_rn(vv.x, vv.y);
            ((__half2*)(vh + j * 4))[1] = __floats2half2_rn(vv.z, vv.w);
        }
    } else {
        uint2 z = {0u, 0u};
        #pragma unroll
        for (int j = 0; j < 4; j++) {
            *(uint2*)(kh + j * 4) = z;
            *(uint2*)(kl + j * 4) = z;
            *(uint2*)(vh + j * 4) = z;
        }
    }
}

// ---------- main attention kernel ----------
extern __shared__ char smem[];

__global__ __launch_bounds__(NTH, 1)
void attn_kernel(const float* __restrict__ Q, float* __restrict__ out) {
    const int b = blockIdx.y;
    const int ncols = g_ccnt[b];
    const int nActive = (ncols + TR - 1) / TR;
    const int tid = threadIdx.x;

    // ---- zero-fill branch: masked rows ----
    if ((int)blockIdx.x >= nActive) {
        const int nmask = S - ncols;
        const int m0 = ((int)blockIdx.x - nActive) * TR;
        if (m0 >= nmask) return;
        const int r = tid >> 4, tg = tid & 15;
        if (m0 + r >= nmask) return;
        const int row = g_midx[b][m0 + r];
        float4 z = {0.f, 0.f, 0.f, 0.f};
        float4* arow = (float4*)(out + (size_t)B * S * D + ((size_t)b * S + row) * S);
        #pragma unroll 8
        for (int it = 0; it < 32; it++) arow[it * 16 + tg] = z;
        *(float4*)(out + ((size_t)b * S + row) * D + tg * 4) = z;
        return;
    }

    const int row0c = blockIdx.x * TR;
    const int nrows = min(TR, ncols - row0c);
    const int lane = tid & 31, w = tid >> 5;
    const int rg = w >> 3, cg = w & 7;
    const int nt = (ncols + TC - 1) / TC;

    __half* sPh  = (__half*)(smem + OFF_PH);
    int*    sPinv= (int*)(smem + OFF_PINV);
    float*  sWsum= (float*)(smem + OFF_WSUM);
    float*  sInv = (float*)(smem + OFF_INV);
    int*    sOrig= (int*)(smem + OFF_ORIG);
    const uint32_t smemBase = (uint32_t)__cvta_generic_to_shared(smem);

    const __half* khB = g_kh + (size_t)b * S * D;
    const __half* klB = g_kl + (size_t)b * S * D;
    const __half* vhB = g_vh + (size_t)b * S * D;

    // ---- prologue: prefetch tiles 0,1 ----
    {
        const int j = tid >> 3, c = tid & 7;   // 64 rows x 8 chunks
        #pragma unroll
        for (int t = 0; t < 2; t++) {
            if (t < nt) {
                const int ct = t * TC;
                uint32_t stg = smemBase + OFF_STAGE + t * STG_STRIDE
                             + (uint32_t)((j * KP + c * 8) * 2);
                size_t gofs = (size_t)(ct + j) * D + c * 8;
                cpa16(stg + STG_KH, khB + gofs);
                cpa16(stg + STG_KL, klB + gofs);
                cpa16(stg + STG_VH, vhB + gofs);
            }
            cpcommit();
        }
    }

    if (tid < 32) sWsum[tid] = 0.f;
    // pinv copy: 2048 ints = exactly 512 int4
    ((int4*)sPinv)[tid] = ((const int4*)&g_pinv[b][0])[tid];

    // ---- Q load + fp16 split (pre-scaled by 1/8) ----
    {
        int r = tid >> 4, f = tid & 15;
        float4 q = {0.f, 0.f, 0.f, 0.f};
        if (r < nrows) {
            int orig = g_cidx[b][row0c + r];
            if (f == 0) sOrig[r] = orig;
            q = ((const float4*)(Q + ((size_t)b * S + orig) * D))[f];
            q.x *= 0.125f; q.y *= 0.125f; q.z *= 0.125f; q.w *= 0.125f;
        }
        __half hx = __float2half_rn(q.x), hy = __float2half_rn(q.y);
        __half hz = __float2half_rn(q.z), hw = __float2half_rn(q.w);
        __half2* dh = (__half2*)(smem + OFF_QH + ((size_t)r * KP + f * 4) * 2);
        dh[0] = __halves2half2(hx, hy);
        dh[1] = __halves2half2(hz, hw);
        __half2* dl = (__half2*)(smem + OFF_QL + ((size_t)r * KP + f * 4) * 2);
        dl[0] = __floats2half2_rn(q.x - __half2float(hx), q.y - __half2float(hy));
        dl[1] = __floats2half2_rn(q.z - __half2float(hz), q.w - __half2float(hw));
    }
    __syncthreads();

    // ---- Q fragments to registers (resident across all tiles) ----
    uint32_t qh[4][4], ql[4][4];
    {
        const uint32_t aQoff =
            (uint32_t)(((rg * 16 + (lane & 15)) * KP + ((lane >> 4) << 3)) * 2);
        #pragma unroll
        for (int kk = 0; kk < 4; kk++) {
            ldsm4(qh[kk][0], qh[kk][1], qh[kk][2], qh[kk][3],
                  smemBase + OFF_QH + aQoff + kk * 32);
            ldsm4(ql[kk][0], ql[kk][1], ql[kk][2], ql[kk][3],
                  smemBase + OFF_QL + aQoff + kk * 32);
        }
    }

    // per-warp geometry
    const uint32_t bKoff =
        (uint32_t)(((cg * 8 + (lane & 7)) * KP) * 2 + (((lane >> 3) & 1) << 4));
    const uint32_t bVoff = (uint32_t)(((lane & 15) * KP + cg * 8) * 2);
    const uint32_t aPoff =
        (uint32_t)(((rg * 16 + (lane & 15)) * PP + ((lane >> 4) << 3)) * 2);
    const int rowE = rg * 16 + (lane >> 2);
    const int colW = cg * 8 + ((lane & 3) << 1);

    float ctx[4] = {0.f, 0.f, 0.f, 0.f};
    float sumLo = 0.f, sumHi = 0.f;

    for (int i = 0; i < nt; i++) {
        const int ct = i * TC;
        const uint32_t stg = smemBase + OFF_STAGE + (i & 1) * STG_STRIDE;
        cpwait1();
        __syncthreads();

        // ---- QK: 3-pass fp16-split, C = 16x8 per warp ----
        float c[4] = {0.f, 0.f, 0.f, 0.f};
        #pragma unroll
        for (int kk = 0; kk < 4; kk++) {
            uint32_t bh0, bh1, bl0, bl1;
            ldsm2(bh0, bh1, stg + STG_KH + bKoff + kk * 32);
            ldsm2(bl0, bl1, stg + STG_KL + bKoff + kk * 32);
            mma16816(c, qh[kk][0], qh[kk][1], qh[kk][2], qh[kk][3], bh0, bh1);
            mma16816(c, qh[kk][0], qh[kk][1], qh[kk][2], qh[kk][3], bl0, bl1);
            mma16816(c, ql[kk][0], ql[kk][1], ql[kk][2], ql[kk][3], bh0, bh1);
        }
        // ---- exp epilogue -> dense compact P + register row sums ----
        {
            const int cb = ct + colW;
            float e0 = (cb     < ncols) ? __expf(c[0]) : 0.f;
            float e1 = (cb + 1 < ncols) ? __expf(c[1]) : 0.f;
            float e2 = (cb     < ncols) ? __expf(c[2]) : 0.f;
            float e3 = (cb + 1 < ncols) ? __expf(c[3]) : 0.f;
            sumLo += e0 + e1;
            sumHi += e2 + e3;
            *(__half2*)&sPh[rowE * PP + cb]       = __floats2half2_rn(e0, e1);
            *(__half2*)&sPh[(rowE + 8) * PP + cb] = __floats2half2_rn(e2, e3);
        }
        __syncthreads();

        // ---- PV: ctx(16x8) += P(16x64) * V(64x8) ----
        #pragma unroll
        for (int ks = 0; ks < 4; ks++) {
            uint32_t a0, a1, a2, a3, b0, b1;
            ldsm4(a0, a1, a2, a3, smemBase + OFF_PH + aPoff + (uint32_t)((ct + ks * 16) * 2));
            ldsm2t(b0, b1, stg + STG_VH + bVoff + (uint32_t)(ks * 16 * KP * 2));
            mma16816(ctx, a0, a1, a2, a3, b0, b1);
        }
        __syncthreads();

        // ---- prefetch tile i+2 into this stage ----
        if (i + 2 < nt) {
            const int j = tid >> 3, cch = tid & 7;
            const int ct2 = (i + 2) * TC;
            uint32_t sdst = stg + (uint32_t)((j * KP + cch * 8) * 2);
            size_t gofs = (size_t)(ct2 + j) * D + cch * 8;
            cpa16(sdst + STG_KH, khB + gofs);
            cpa16(sdst + STG_KL, klB + gofs);
            cpa16(sdst + STG_VH, vhB + gofs);
        }
        cpcommit();
    }

    // ---- row sums ----
    sumLo += __shfl_xor_sync(0xffffffffu, sumLo, 1);
    sumLo += __shfl_xor_sync(0xffffffffu, sumLo, 2);
    sumHi += __shfl_xor_sync(0xffffffffu, sumHi, 1);
    sumHi += __shfl_xor_sync(0xffffffffu, sumHi, 2);
    if ((lane & 3) == 0) {
        atomicAdd(&sWsum[rowE], sumLo);
        atomicAdd(&sWsum[rowE + 8], sumHi);
    }
    __syncthreads();
    if (tid < 32) {
        float t = sWsum[tid];
        sInv[tid] = (t > 0.f) ? (1.f / t) : 0.f;
    }
    __syncthreads();

    // ---- context write ----
    {
        if (rowE < nrows) {
            float inv = sInv[rowE];
            *(float2*)(out + ((size_t)b * S + sOrig[rowE]) * D + colW) =
                make_float2(ctx[0] * inv, ctx[1] * inv);
        }
        if (rowE + 8 < nrows) {
            float inv = sInv[rowE + 8];
            *(float2*)(out + ((size_t)b * S + sOrig[rowE + 8]) * D + colW) =
                make_float2(ctx[2] * inv, ctx[3] * inv);
        }
    }

    // ---- dense attn write: gather via pinv, coalesced float4 stores ----
    {
        const int r = tid >> 4, tg = tid & 15;
        if (r < nrows) {
            const float inv = sInv[r];
            const int orig = sOrig[r];
            const __half* prow = &sPh[r * PP];
            float4* dst = (float4*)(out + (size_t)B * S * D + ((size_t)b * S + orig) * S);
            #pragma unroll 4
            for (int it = 0; it < 32; it++) {
                int cb = it * 16 + tg;
                int4 pv = ((const int4*)sPinv)[cb];
                float4 o;
                o.x = (pv.x >= 0) ? __half2float(prow[pv.x]) * inv : 0.f;
                o.y = (pv.y >= 0) ? __half2float(prow[pv.y]) * inv : 0.f;
                o.z = (pv.z >= 0) ? __half2float(prow[pv.z]) * inv : 0.f;
                o.w = (pv.w >= 0) ? __half2float(prow[pv.w]) * inv : 0.f;
                dst[cb] = o;
            }
        }
    }
}

extern "C" void kernel_launch(void* const* d_in, const int* in_sizes, int n_in,
                              void* d_out, int out_size) {
    const float* Q = (const float*)d_in[0];
    const float* K = (const float*)d_in[1];
    const float* V = (const float*)d_in[2];
    const void*  M = d_in[3];
    float* out = (float*)d_out;

    cudaFuncSetAttribute(attn_kernel, cudaFuncAttributeMaxDynamicSharedMemorySize,
                         SMEM_BYTES);

    build_mask_kernel<<<B, 256>>>(M);
    preprocess_kernel<<<dim3(S / 64, B), 256>>>(K, V);
    attn_kernel<<<dim3(65, B), NTH, SMEM_BYTES>>>(Q, out);
}

// round 5
// speedup vs baseline: 8.0731x; 1.0150x over previous
#include <cuda_runtime.h>
#include <cuda_fp16.h>
#include <cstdint>

#define B 16
#define S 2048
#define D 64
#define TR 32
#define TC 64
#define NTH 512
#define KP 72          // halves pitch for K/V smem rows (144 B)
#define PP 2056        // halves pitch for dense compact P rows (4112 B)

// ---- smem byte offsets ----
#define OFF_PH    0                      // 32 x 2056 half = 131584
#define OFF_STAGE 131584                 // 3 stages x 18432 (phase1: KH+KL; phase2: V)
#define STG_STRIDE 18432
#define STG_KH 0
#define STG_KL 9216
#define OFF_QH    186880                 // 4608
#define OFF_QL    191488                 // 4608
#define OFF_PINV  196096                 // 8192
#define OFF_WSUM  204288                 // 128
#define OFF_INV   204416                 // 128
#define OFF_ORIG  204544                 // 128
#define SMEM_BYTES 204672

// ---------- device scratch ----------
__device__ int g_cidx[B][S];
__device__ int g_midx[B][S];
__device__ int g_pinv[B][S];
__device__ int g_ccnt[B];
__device__ __half g_kh[(size_t)B * S * D];
__device__ __half g_kl[(size_t)B * S * D];
__device__ __half g_vh[(size_t)B * S * D];

// ---------- asm helpers ----------
__device__ __forceinline__ void ldsm4(uint32_t& r0, uint32_t& r1, uint32_t& r2,
                                      uint32_t& r3, uint32_t a) {
    asm volatile("ldmatrix.sync.aligned.m8n8.x4.shared.b16 {%0,%1,%2,%3}, [%4];"
                 : "=r"(r0), "=r"(r1), "=r"(r2), "=r"(r3) : "r"(a));
}
__device__ __forceinline__ void ldsm2(uint32_t& r0, uint32_t& r1, uint32_t a) {
    asm volatile("ldmatrix.sync.aligned.m8n8.x2.shared.b16 {%0,%1}, [%2];"
                 : "=r"(r0), "=r"(r1) : "r"(a));
}
__device__ __forceinline__ void ldsm2t(uint32_t& r0, uint32_t& r1, uint32_t a) {
    asm volatile("ldmatrix.sync.aligned.m8n8.x2.trans.shared.b16 {%0,%1}, [%2];"
                 : "=r"(r0), "=r"(r1) : "r"(a));
}
__device__ __forceinline__ void mma16816(float* d, uint32_t a0, uint32_t a1,
                                         uint32_t a2, uint32_t a3,
                                         uint32_t b0, uint32_t b1) {
    asm volatile(
        "mma.sync.aligned.m16n8k16.row.col.f32.f16.f16.f32 "
        "{%0,%1,%2,%3},{%4,%5,%6,%7},{%8,%9},{%0,%1,%2,%3};"
        : "+f"(d[0]), "+f"(d[1]), "+f"(d[2]), "+f"(d[3])
        : "r"(a0), "r"(a1), "r"(a2), "r"(a3), "r"(b0), "r"(b1));
}
__device__ __forceinline__ void cpa16(uint32_t saddr, const void* g) {
    asm volatile("cp.async.cg.shared.global [%0], [%1], 16;" :: "r"(saddr), "l"(g)
                 : "memory");
}
__device__ __forceinline__ void cpcommit() {
    asm volatile("cp.async.commit_group;" ::: "memory");
}
__device__ __forceinline__ void cpwait1() {
    asm volatile("cp.async.wait_group 1;" ::: "memory");
}
__device__ __forceinline__ void cpwait0() {
    asm volatile("cp.async.wait_group 0;" ::: "memory");
}
__device__ __forceinline__ void barhalf() {   // warps 0-7 only
    asm volatile("bar.sync 1, 256;" ::: "memory");
}

// ---------- mask build ----------
__global__ void build_mask_kernel(const void* mptr) {
    const int b = blockIdx.x;
    const int tid = threadIdx.x;
    __shared__ int warpTot[8];
    __shared__ int okInt, okFlt;
    const unsigned char* pb = (const unsigned char*)mptr;
    if (tid == 0) { okInt = 1; okFlt = 1; }
    __syncthreads();
    {
        unsigned char b0 = pb[4*tid], b1 = pb[4*tid+1], b2 = pb[4*tid+2], b3 = pb[4*tid+3];
        bool gi = (b0 <= 1 && b1 == 0 && b2 == 0 && b3 == 0);
        bool zf = (b0 == 0 && b1 == 0 && b2 == 0 && b3 == 0);
        bool of = (b0 == 0 && b1 == 0 && b2 == 0x80 && b3 == 0x3f);
        if (!gi) atomicExch(&okInt, 0);
        if (!(zf || of)) atomicExch(&okFlt, 0);
    }
    __syncthreads();
    const int mode = okInt ? 1 : (okFlt ? 2 : 0);
    unsigned char mloc[8];
    int cnt = 0;
    #pragma unroll
    for (int k = 0; k < 8; k++) {
        int i = b * S + tid * 8 + k;
        unsigned char m;
        if (mode == 1)      m = (((const int*)mptr)[i] != 0);
        else if (mode == 2) m = (((const float*)mptr)[i] != 0.0f);
        else                m = (pb[i] != 0);
        mloc[k] = m;
        cnt += (m == 0);
    }
    int lane = tid & 31, w = tid >> 5;
    int x = cnt;
    #pragma unroll
    for (int off = 1; off < 32; off <<= 1) {
        int y = __shfl_up_sync(0xffffffffu, x, off);
        if (lane >= off) x += y;
    }
    if (lane == 31) warpTot[w] = x;
    __syncthreads();
    int wOff = 0;
    for (int ww = 0; ww < w; ww++) wOff += warpTot[ww];
    int pos = wOff + x - cnt;
    #pragma unroll
    for (int k = 0; k < 8; k++) {
        int idx = tid * 8 + k;
        if (!mloc[k]) {
            g_cidx[b][pos] = idx;
            g_pinv[b][idx] = pos;
            pos++;
        } else {
            g_midx[b][idx - pos] = idx;
            g_pinv[b][idx] = -1;
        }
    }
    if (tid == 255) g_ccnt[b] = pos;
}

// ---------- preprocess: K/V -> fp16 (K split hi/lo) in compact order ----------
__global__ void preprocess_kernel(const float* __restrict__ K,
                                  const float* __restrict__ V) {
    const int b = blockIdx.y;
    const int tid = threadIdx.x;
    const int cc = blockIdx.x * 64 + (tid >> 2);
    const int qd = (tid & 3) * 16;
    const int nc = g_ccnt[b];
    __half* kh = g_kh + ((size_t)b * S + cc) * D + qd;
    __half* kl = g_kl + ((size_t)b * S + cc) * D + qd;
    __half* vh = g_vh + ((size_t)b * S + cc) * D + qd;
    if (cc < nc) {
        int orig = g_cidx[b][cc];
        const float4* kp = (const float4*)(K + ((size_t)b * S + orig) * D + qd);
        const float4* vp = (const float4*)(V + ((size_t)b * S + orig) * D + qd);
        #pragma unroll
        for (int j = 0; j < 4; j++) {
            float4 kv = kp[j], vv = vp[j];
            __half h0 = __float2half_rn(kv.x), h1 = __float2half_rn(kv.y);
            __half h2 = __float2half_rn(kv.z), h3 = __float2half_rn(kv.w);
            ((__half2*)(kh + j * 4))[0] = __halves2half2(h0, h1);
            ((__half2*)(kh + j * 4))[1] = __halves2half2(h2, h3);
            ((__half2*)(kl + j * 4))[0] =
                __floats2half2_rn(kv.x - __half2float(h0), kv.y - __half2float(h1));
            ((__half2*)(kl + j * 4))[1] =
                __floats2half2_rn(kv.z - __half2float(h2), kv.w - __half2float(h3));
            ((__half2*)(vh + j * 4))[0] = __floats2half2_rn(vv.x, vv.y);
            ((__half2*)(vh + j * 4))[1] = __floats2half2_rn(vv.z, vv.w);
        }
    } else {
        uint2 z = {0u, 0u};
        #pragma unroll
        for (int j = 0; j < 4; j++) {
            *(uint2*)(kh + j * 4) = z;
            *(uint2*)(kl + j * 4) = z;
            *(uint2*)(vh + j * 4) = z;
        }
    }
}

// ---------- main attention kernel ----------
extern __shared__ char smem[];

__global__ __launch_bounds__(NTH, 1)
void attn_kernel(const float* __restrict__ Q, float* __restrict__ out) {
    const int b = blockIdx.y;
    const int ncols = g_ccnt[b];
    const int nActive = (ncols + TR - 1) / TR;
    const int tid = threadIdx.x;

    // ---- zero-fill branch: masked rows ----
    if ((int)blockIdx.x >= nActive) {
        const int nmask = S - ncols;
        const int m0 = ((int)blockIdx.x - nActive) * TR;
        if (m0 >= nmask) return;
        const int r = tid >> 4, tg = tid & 15;
        if (m0 + r >= nmask) return;
        const int row = g_midx[b][m0 + r];
        float4 z = {0.f, 0.f, 0.f, 0.f};
        float4* arow = (float4*)(out + (size_t)B * S * D + ((size_t)b * S + row) * S);
        #pragma unroll 8
        for (int it = 0; it < 32; it++) arow[it * 16 + tg] = z;
        *(float4*)(out + ((size_t)b * S + row) * D + tg * 4) = z;
        return;
    }

    const int row0c = blockIdx.x * TR;
    const int nrows = min(TR, ncols - row0c);
    const int lane = tid & 31, w = tid >> 5;
    const int rg = w >> 3, cg = w & 7;
    const int nt = (ncols + TC - 1) / TC;

    __half* sPh  = (__half*)(smem + OFF_PH);
    int*    sPinv= (int*)(smem + OFF_PINV);
    float*  sWsum= (float*)(smem + OFF_WSUM);
    float*  sInv = (float*)(smem + OFF_INV);
    int*    sOrig= (int*)(smem + OFF_ORIG);
    const uint32_t smemBase = (uint32_t)__cvta_generic_to_shared(smem);

    const __half* khB = g_kh + (size_t)b * S * D;
    const __half* klB = g_kl + (size_t)b * S * D;
    const __half* vhB = g_vh + (size_t)b * S * D;

    // ---- phase-1 prologue: prefetch K tiles 0,1 (hi+lo) ----
    {
        const int j = tid >> 3, c = tid & 7;   // 64 rows x 8 chunks
        #pragma unroll
        for (int t = 0; t < 2; t++) {
            if (t < nt) {
                uint32_t stg = smemBase + OFF_STAGE + t * STG_STRIDE
                             + (uint32_t)((j * KP + c * 8) * 2);
                size_t gofs = (size_t)(t * TC + j) * D + c * 8;
                cpa16(stg + STG_KH, khB + gofs);
                cpa16(stg + STG_KL, klB + gofs);
            }
            cpcommit();
        }
    }

    if (tid < 32) sWsum[tid] = 0.f;
    ((int4*)sPinv)[tid] = ((const int4*)&g_pinv[b][0])[tid];

    // ---- Q load + fp16 split (pre-scaled by 1/8) ----
    {
        int r = tid >> 4, f = tid & 15;
        float4 q = {0.f, 0.f, 0.f, 0.f};
        if (r < nrows) {
            int orig = g_cidx[b][row0c + r];
            if (f == 0) sOrig[r] = orig;
            q = ((const float4*)(Q + ((size_t)b * S + orig) * D))[f];
            q.x *= 0.125f; q.y *= 0.125f; q.z *= 0.125f; q.w *= 0.125f;
        }
        __half hx = __float2half_rn(q.x), hy = __float2half_rn(q.y);
        __half hz = __float2half_rn(q.z), hw = __float2half_rn(q.w);
        __half2* dh = (__half2*)(smem + OFF_QH + ((size_t)r * KP + f * 4) * 2);
        dh[0] = __halves2half2(hx, hy);
        dh[1] = __halves2half2(hz, hw);
        __half2* dl = (__half2*)(smem + OFF_QL + ((size_t)r * KP + f * 4) * 2);
        dl[0] = __floats2half2_rn(q.x - __half2float(hx), q.y - __half2float(hy));
        dl[1] = __floats2half2_rn(q.z - __half2float(hz), q.w - __half2float(hw));
    }
    __syncthreads();

    // ---- Q fragments to registers ----
    uint32_t qh[4][4], ql[4][4];
    {
        const uint32_t aQoff =
            (uint32_t)(((rg * 16 + (lane & 15)) * KP + ((lane >> 4) << 3)) * 2);
        #pragma unroll
        for (int kk = 0; kk < 4; kk++) {
            ldsm4(qh[kk][0], qh[kk][1], qh[kk][2], qh[kk][3],
                  smemBase + OFF_QH + aQoff + kk * 32);
            ldsm4(ql[kk][0], ql[kk][1], ql[kk][2], ql[kk][3],
                  smemBase + OFF_QL + aQoff + kk * 32);
        }
    }

    const uint32_t bKoff =
        (uint32_t)(((cg * 8 + (lane & 7)) * KP) * 2 + (((lane >> 3) & 1) << 4));
    const int rowE = rg * 16 + (lane >> 2);
    const int colW = cg * 8 + ((lane & 3) << 1);

    float sumLo = 0.f, sumHi = 0.f;

    // ================= PHASE 1: QK + exp (1 sync/tile, 3-stage K ring) ==========
    for (int i = 0; i < nt; i++) {
        const int ct = i * TC;
        const uint32_t stg = smemBase + OFF_STAGE + (uint32_t)((i % 3) * STG_STRIDE);
        cpwait1();
        __syncthreads();

        float c[4] = {0.f, 0.f, 0.f, 0.f};
        #pragma unroll
        for (int kk = 0; kk < 4; kk++) {
            uint32_t bh0, bh1, bl0, bl1;
            ldsm2(bh0, bh1, stg + STG_KH + bKoff + kk * 32);
            ldsm2(bl0, bl1, stg + STG_KL + bKoff + kk * 32);
            mma16816(c, qh[kk][0], qh[kk][1], qh[kk][2], qh[kk][3], bh0, bh1);
            mma16816(c, qh[kk][0], qh[kk][1], qh[kk][2], qh[kk][3], bl0, bl1);
            mma16816(c, ql[kk][0], ql[kk][1], ql[kk][2], ql[kk][3], bh0, bh1);
        }
        {
            const int cb = ct + colW;
            float e0 = (cb     < ncols) ? __expf(c[0]) : 0.f;
            float e1 = (cb + 1 < ncols) ? __expf(c[1]) : 0.f;
            float e2 = (cb     < ncols) ? __expf(c[2]) : 0.f;
            float e3 = (cb + 1 < ncols) ? __expf(c[3]) : 0.f;
            sumLo += e0 + e1;
            sumHi += e2 + e3;
            *(__half2*)&sPh[rowE * PP + cb]       = __floats2half2_rn(e0, e1);
            *(__half2*)&sPh[(rowE + 8) * PP + cb] = __floats2half2_rn(e2, e3);
        }
        if (i + 2 < nt) {
            const int j = tid >> 3, cch = tid & 7;
            uint32_t sdst = smemBase + OFF_STAGE
                          + (uint32_t)(((i + 2) % 3) * STG_STRIDE)
                          + (uint32_t)((j * KP + cch * 8) * 2);
            size_t gofs = (size_t)((i + 2) * TC + j) * D + cch * 8;
            cpa16(sdst + STG_KH, khB + gofs);
            cpa16(sdst + STG_KL, klB + gofs);
        }
        cpcommit();
    }

    // ---- row sums -> sInv ----
    sumLo += __shfl_xor_sync(0xffffffffu, sumLo, 1);
    sumLo += __shfl_xor_sync(0xffffffffu, sumLo, 2);
    sumHi += __shfl_xor_sync(0xffffffffu, sumHi, 1);
    sumHi += __shfl_xor_sync(0xffffffffu, sumHi, 2);
    if ((lane & 3) == 0) {
        atomicAdd(&sWsum[rowE], sumLo);
        atomicAdd(&sWsum[rowE + 8], sumHi);
    }
    __syncthreads();
    if (tid < 32) {
        float t = sWsum[tid];
        sInv[tid] = (t > 0.f) ? (1.f / t) : 0.f;
    }
    __syncthreads();

    // ================= PHASE 2: warp-specialized PV || attn writeback ===========
    if (w < 8) {
        // ---- PV warps (0-7): ctx for rows 0-15 & 16-31, cols w*8..w*8+7 ----
        cpwait0();
        {   // V prologue: tiles 0,1
            const int j = tid >> 2, c0 = (tid & 3) * 2;
            #pragma unroll
            for (int t = 0; t < 2; t++) {
                if (t < nt) {
                    uint32_t stg = smemBase + OFF_STAGE + t * STG_STRIDE;
                    #pragma unroll
                    for (int u = 0; u < 2; u++) {
                        cpa16(stg + (uint32_t)((j * KP + (c0 + u) * 8) * 2),
                              vhB + (size_t)(t * TC + j) * D + (c0 + u) * 8);
                    }
                }
                cpcommit();
            }
        }
        const uint32_t bVoff = (uint32_t)(((lane & 15) * KP + cg * 8) * 2);
        const uint32_t aP0 =
            (uint32_t)(((lane & 15) * PP + ((lane >> 4) << 3)) * 2);
        const uint32_t aP1 = aP0 + (uint32_t)(16 * PP * 2);

        float ctx0[4] = {0.f, 0.f, 0.f, 0.f};
        float ctx1[4] = {0.f, 0.f, 0.f, 0.f};

        for (int i = 0; i < nt; i++) {
            const int ct = i * TC;
            const uint32_t stg = smemBase + OFF_STAGE + (uint32_t)((i % 3) * STG_STRIDE);
            cpwait1();
            barhalf();
            #pragma unroll
            for (int ks = 0; ks < 4; ks++) {
                uint32_t a0, a1, a2, a3, b0, b1;
                ldsm2t(b0, b1, stg + bVoff + (uint32_t)(ks * 16 * KP * 2));
                ldsm4(a0, a1, a2, a3,
                      smemBase + OFF_PH + aP0 + (uint32_t)((ct + ks * 16) * 2));
                mma16816(ctx0, a0, a1, a2, a3, b0, b1);
                ldsm4(a0, a1, a2, a3,
                      smemBase + OFF_PH + aP1 + (uint32_t)((ct + ks * 16) * 2));
                mma16816(ctx1, a0, a1, a2, a3, b0, b1);
            }
            if (i + 2 < nt) {
                const int j = tid >> 2, c0 = (tid & 3) * 2;
                uint32_t sdst = smemBase + OFF_STAGE
                              + (uint32_t)(((i + 2) % 3) * STG_STRIDE);
                #pragma unroll
                for (int u = 0; u < 2; u++) {
                    cpa16(sdst + (uint32_t)((j * KP + (c0 + u) * 8) * 2),
                          vhB + (size_t)((i + 2) * TC + j) * D + (c0 + u) * 8);
                }
            }
            cpcommit();
        }
        // ---- context write ----
        {
            const int r0 = lane >> 2;
            if (r0 < nrows) {
                float inv = sInv[r0];
                *(float2*)(out + ((size_t)b * S + sOrig[r0]) * D + colW) =
                    make_float2(ctx0[0] * inv, ctx0[1] * inv);
            }
            if (r0 + 8 < nrows) {
                float inv = sInv[r0 + 8];
                *(float2*)(out + ((size_t)b * S + sOrig[r0 + 8]) * D + colW) =
                    make_float2(ctx0[2] * inv, ctx0[3] * inv);
            }
            if (r0 + 16 < nrows) {
                float inv = sInv[r0 + 16];
                *(float2*)(out + ((size_t)b * S + sOrig[r0 + 16]) * D + colW) =
                    make_float2(ctx1[0] * inv, ctx1[1] * inv);
            }
            if (r0 + 24 < nrows) {
                float inv = sInv[r0 + 24];
                *(float2*)(out + ((size_t)b * S + sOrig[r0 + 24]) * D + colW) =
                    make_float2(ctx1[2] * inv, ctx1[3] * inv);
            }
        }
    } else {
        // ---- writeback warps (8-15): 4 attn rows each, pinv gather ----
        cpwait0();
        const int wr = w - 8;
        #pragma unroll
        for (int rr = 0; rr < 4; rr++) {
            const int r = wr * 4 + rr;
            if (r >= nrows) continue;
            const float inv = sInv[r];
            const int orig = sOrig[r];
            const __half* prow = &sPh[r * PP];
            float4* dst = (float4*)(out + (size_t)B * S * D + ((size_t)b * S + orig) * S);
            #pragma unroll 4
            for (int it = 0; it < 16; it++) {
                int cb = it * 32 + lane;
                int4 pv = ((const int4*)sPinv)[cb];
                float4 o;
                o.x = (pv.x >= 0) ? __half2float(prow[pv.x]) * inv : 0.f;
                o.y = (pv.y >= 0) ? __half2float(prow[pv.y]) * inv : 0.f;
                o.z = (pv.z >= 0) ? __half2float(prow[pv.z]) * inv : 0.f;
                o.w = (pv.w >= 0) ? __half2float(prow[pv.w]) * inv : 0.f;
                dst[cb] = o;
            }
        }
    }
}

extern "C" void kernel_launch(void* const* d_in, const int* in_sizes, int n_in,
                              void* d_out, int out_size) {
    const float* Q = (const float*)d_in[0];
    const float* K = (const float*)d_in[1];
    const float* V = (const float*)d_in[2];
    const void*  M = d_in[3];
    float* out = (float*)d_out;

    cudaFuncSetAttribute(attn_kernel, cudaFuncAttributeMaxDynamicSharedMemorySize,
                         SMEM_BYTES);

    build_mask_kernel<<<B, 256>>>(M);
    preprocess_kernel<<<dim3(S / 64, B), 256>>>(K, V);
    attn_kernel<<<dim3(65, B), NTH, SMEM_BYTES>>>(Q, out);
}